// round 1
// baseline (speedup 1.0000x reference)
#include <cuda_runtime.h>
#include <math.h>

#define BB 16384
#define XD 2000
#define HD 100
#define ZD 20
#define KTOT (2*XD)      // 4000
#define LN_EPS 1e-5f

// ---------------- scratch (static device globals; no allocations) -------------
__device__ float g_h1 [(size_t)BB*HD];
__device__ float g_h1g[(size_t)BB*HD];
__device__ float g_th [(size_t)BB*HD];
__device__ float g_ld [(size_t)BB*XD];
__device__ float g_tld[(size_t)BB*XD];
__device__ float g_sld [BB];
__device__ float g_stld[BB];
__device__ float g_beta [XD];
__device__ float g_gamma[XD];

// ---------------- helpers -----------------------------------------------------
__device__ __forceinline__ float softplusf(float x) {
    return fmaxf(x, 0.f) + log1pf(expf(-fabsf(x)));
}
__device__ __forceinline__ float sigmoidf(float x) {
    return 1.f / (1.f + expf(-x));
}
__device__ __forceinline__ float geluf(float x) {
    return 0.5f * x * (1.f + erff(x * 0.70710678118654752f));
}
__device__ __forceinline__ float wsum(float v) {
#pragma unroll
    for (int o = 16; o; o >>= 1) v += __shfl_xor_sync(0xffffffffu, v, o);
    return v;
}

// ---------------- k0: beta/gamma precompute ----------------------------------
__global__ void k0_rates(const float* __restrict__ lb, const float* __restrict__ lg) {
    int i = blockIdx.x * blockDim.x + threadIdx.x;
    if (i < XD) {
        g_beta[i]  = softplusf(lb[i]);   // * DT (=1)
        g_gamma[i] = softplusf(lg[i]);
    }
}

// ---------------- k1: h1 = gelu(LN([s,u]@W1 + b1)) ----------------------------
// block: 256 threads = (tx 32) x (ty 8); tile M=64 rows, N=128 (100 valid), Kc=16
__global__ void __launch_bounds__(256) k1_enc1(
    const float* __restrict__ s, const float* __restrict__ u,
    const float* __restrict__ w1, const float* __restrict__ b1)
{
    __shared__ float As[16][64];    // [k][m]
    __shared__ float Ws[16][128];   // [k][n], zero-padded n>=100

    int tid = threadIdx.x;
    int tx = tid & 31, ty = tid >> 5;
    int m0 = blockIdx.x * 64;

    float acc[8][4];
#pragma unroll
    for (int i = 0; i < 8; i++)
#pragma unroll
        for (int j = 0; j < 4; j++) acc[i][j] = 0.f;

    float bv[4];
#pragma unroll
    for (int j = 0; j < 4; j++) {
        int n = tx * 4 + j;
        bv[j] = (n < HD) ? b1[n] : 0.f;
    }

    for (int kb = 0; kb < KTOT; kb += 16) {
        // load A tile: each thread one float4 (m = tid>>2, k4 = (tid&3)*4)
        {
            int m  = tid >> 2;
            int k4 = (tid & 3) * 4;
            int gk = kb + k4;
            float4 v;
            if (gk < XD) v = *(const float4*)&s[(size_t)(m0 + m) * XD + gk];
            else         v = *(const float4*)&u[(size_t)(m0 + m) * XD + gk - XD];
            As[k4 + 0][m] = v.x; As[k4 + 1][m] = v.y;
            As[k4 + 2][m] = v.z; As[k4 + 3][m] = v.w;
        }
        // load W tile: 16x128, 8 elems/thread
#pragma unroll
        for (int t = 0; t < 8; t++) {
            int lin = tid + t * 256;
            int n = lin & 127, k = lin >> 7;
            Ws[k][n] = (n < HD) ? w1[(size_t)(kb + k) * HD + n] : 0.f;
        }
        __syncthreads();

#pragma unroll
        for (int k = 0; k < 16; k++) {
            float4 w  = *(const float4*)&Ws[k][tx * 4];
            float4 a0 = *(const float4*)&As[k][ty * 8];
            float4 a1 = *(const float4*)&As[k][ty * 8 + 4];
            float av[8] = {a0.x, a0.y, a0.z, a0.w, a1.x, a1.y, a1.z, a1.w};
#pragma unroll
            for (int i = 0; i < 8; i++) {
                acc[i][0] += av[i] * w.x;
                acc[i][1] += av[i] * w.y;
                acc[i][2] += av[i] * w.z;
                acc[i][3] += av[i] * w.w;
            }
        }
        __syncthreads();
    }

    // per-row LN (100 valid values spread across warp lanes) + GELU
#pragma unroll
    for (int i = 0; i < 8; i++) {
        int m = m0 + ty * 8 + i;
        float x[4], sm = 0.f, sq = 0.f;
#pragma unroll
        for (int j = 0; j < 4; j++) {
            x[j] = acc[i][j] + bv[j];      // invalid lanes: acc=0, bv=0
            sm += x[j];
            sq += x[j] * x[j];
        }
        sm = wsum(sm); sq = wsum(sq);
        float mean = sm * (1.f / HD);
        float var  = sq * (1.f / HD) - mean * mean;
        float rs = rsqrtf(var + LN_EPS);
        if (tx < 25) {
            float4 o;
            o.x = geluf((x[0] - mean) * rs);
            o.y = geluf((x[1] - mean) * rs);
            o.z = geluf((x[2] - mean) * rs);
            o.w = geluf((x[3] - mean) * rs);
            *(float4*)&g_h1[(size_t)m * HD + tx * 4] = o;
        }
    }
}

// ---------------- k2: everything small, one warp per row ----------------------
#define K2_SMEM_FLOATS (22380 + 8*264)
__global__ void __launch_bounds__(256) k2_mid(
    const float* __restrict__ eps_z, const float* __restrict__ eps_d,
    const float* __restrict__ w2, const float* __restrict__ b2,
    const float* __restrict__ wmu, const float* __restrict__ bmu,
    const float* __restrict__ wlv, const float* __restrict__ blv,
    const float* __restrict__ edw1, const float* __restrict__ edb1,
    const float* __restrict__ edwmu, const float* __restrict__ edbmu,
    const float* __restrict__ edwlv, const float* __restrict__ edblv,
    const float* __restrict__ dzw1, const float* __restrict__ dzb1,
    float* __restrict__ o_z, float* __restrict__ o_dz,
    float* __restrict__ o_muz, float* __restrict__ o_scz,
    float* __restrict__ o_mud, float* __restrict__ o_scd)
{
    extern __shared__ float sm2[];
    float* sw2    = sm2;              // 10000
    float* swmu   = sw2 + 10000;      // 2000
    float* swlv   = swmu + 2000;      // 2000
    float* sb2    = swlv + 2000;      // 100
    float* sbmu   = sb2 + 100;        // 20
    float* sblv   = sbmu + 20;        // 20
    float* sedw1  = sblv + 20;        // 2000
    float* sedb1  = sedw1 + 2000;     // 100
    float* sedwmu = sedb1 + 100;      // 2000
    float* sedbmu = sedwmu + 2000;    // 20
    float* sedwlv = sedbmu + 20;      // 2000
    float* sedblv = sedwlv + 2000;    // 20
    float* sdzw1  = sedblv + 20;      // 2000
    float* sdzb1  = sdzw1 + 2000;     // 100
    float* wbuf   = sdzb1 + 100;      // 8 warps * 264

    {
        int t = threadIdx.x, nt = blockDim.x;
        for (int i = t; i < 10000; i += nt) sw2[i] = w2[i];
        for (int i = t; i < 2000; i += nt) { swmu[i] = wmu[i]; swlv[i] = wlv[i]; }
        for (int i = t; i < 2000; i += nt) { sedw1[i] = edw1[i]; sdzw1[i] = dzw1[i]; }
        for (int i = t; i < 2000; i += nt) { sedwmu[i] = edwmu[i]; sedwlv[i] = edwlv[i]; }
        for (int i = t; i < 100; i += nt) { sb2[i] = b2[i]; sedb1[i] = edb1[i]; sdzb1[i] = dzb1[i]; }
        if (t < 20) { sbmu[t] = bmu[t]; sblv[t] = blv[t]; sedbmu[t] = edbmu[t]; sedblv[t] = edblv[t]; }
    }
    __syncthreads();

    int wid = threadIdx.x >> 5, lane = threadIdx.x & 31;
    float* B0 = wbuf + wid * 264;
    float* B1 = B0 + 132;
    int nwarps = gridDim.x * 8;

    for (int r = blockIdx.x * 8 + wid; r < BB; r += nwarps) {
        // load h1 row
        for (int i = lane; i < HD; i += 32) B0[i] = g_h1[(size_t)r * HD + i];
        __syncwarp();

        // ---- h2 = gelu(LN(h1@w2 + b2)) ----
        float x[4];
#pragma unroll
        for (int j = 0; j < 4; j++) {
            int n = lane + 32 * j;
            float acc = 0.f;
            if (n < HD) {
                acc = sb2[n];
                for (int k = 0; k < HD; k++) acc += B0[k] * sw2[k * HD + n];
            }
            x[j] = acc;
        }
        float smv = x[0] + x[1] + x[2] + x[3];
        float sqv = x[0]*x[0] + x[1]*x[1] + x[2]*x[2] + x[3]*x[3];
        smv = wsum(smv); sqv = wsum(sqv);
        float mean = smv * (1.f / HD);
        float rs = rsqrtf(sqv * (1.f / HD) - mean * mean + LN_EPS);
#pragma unroll
        for (int j = 0; j < 4; j++) {
            int n = lane + 32 * j;
            if (n < HD) B1[n] = geluf((x[j] - mean) * rs);
        }
        __syncwarp();

        // ---- z heads ----
        if (lane < ZD) {
            float mu = sbmu[lane], lv = sblv[lane];
            for (int k = 0; k < HD; k++) {
                float h = B1[k];
                mu += h * swmu[k * ZD + lane];
                lv += h * swlv[k * ZD + lane];
            }
            float sc = softplusf(lv);
            float z = mu + sc * eps_z[(size_t)r * ZD + lane];
            o_z  [(size_t)r * ZD + lane] = z;
            o_muz[(size_t)r * ZD + lane] = mu;
            o_scz[(size_t)r * ZD + lane] = sc;
            B0[lane] = z;
        }
        __syncwarp();

        // ---- hd = gelu(LN(z@ed_w1 + b)) ----
#pragma unroll
        for (int j = 0; j < 4; j++) {
            int n = lane + 32 * j;
            float acc = 0.f;
            if (n < HD) {
                acc = sedb1[n];
                for (int k = 0; k < ZD; k++) acc += B0[k] * sedw1[k * HD + n];
            }
            x[j] = acc;
        }
        smv = x[0] + x[1] + x[2] + x[3];
        sqv = x[0]*x[0] + x[1]*x[1] + x[2]*x[2] + x[3]*x[3];
        smv = wsum(smv); sqv = wsum(sqv);
        mean = smv * (1.f / HD);
        rs = rsqrtf(sqv * (1.f / HD) - mean * mean + LN_EPS);
#pragma unroll
        for (int j = 0; j < 4; j++) {
            int n = lane + 32 * j;
            if (n < HD) B1[n] = geluf((x[j] - mean) * rs);
        }
        __syncwarp();

        // ---- d heads ----
        if (lane < ZD) {
            float mu = sedbmu[lane], lv = sedblv[lane];
            for (int k = 0; k < HD; k++) {
                float h = B1[k];
                mu += h * sedwmu[k * ZD + lane];
                lv += h * sedwlv[k * ZD + lane];
            }
            float sc = softplusf(lv);
            float dz = mu + sc * eps_d[(size_t)r * ZD + lane];
            o_dz [(size_t)r * ZD + lane] = dz;
            o_mud[(size_t)r * ZD + lane] = mu;
            o_scd[(size_t)r * ZD + lane] = sc;
            B0[32 + lane] = dz;
        }
        __syncwarp();

        // ---- decoder layer 1 with JVP: a1 = z@w1+b, t1 = dz@w1 ----
        float a[4], t[4];
#pragma unroll
        for (int j = 0; j < 4; j++) {
            int n = lane + 32 * j;
            float aa = 0.f, tt = 0.f;
            if (n < HD) {
                aa = sdzb1[n];
                for (int k = 0; k < ZD; k++) {
                    float w = sdzw1[k * HD + n];
                    aa += B0[k] * w;
                    tt += B0[32 + k] * w;
                }
            }
            a[j] = aa; t[j] = tt;
        }
        float sa = a[0]+a[1]+a[2]+a[3];
        float saa = a[0]*a[0]+a[1]*a[1]+a[2]*a[2]+a[3]*a[3];
        float st = t[0]+t[1]+t[2]+t[3];
        float sat = a[0]*t[0]+a[1]*t[1]+a[2]*t[2]+a[3]*t[3];
        sa = wsum(sa); saa = wsum(saa); st = wsum(st); sat = wsum(sat);
        float m  = sa * (1.f / HD);
        float v  = saa * (1.f / HD) - m * m;
        float r2 = rsqrtf(v + LN_EPS);
        float dm = st * (1.f / HD);
        float dv = 2.f * (sat * (1.f / HD) - m * dm);
#pragma unroll
        for (int j = 0; j < 4; j++) {
            int n = lane + 32 * j;
            if (n < HD) {
                float y  = (a[j] - m) * r2;
                float dy = r2 * (t[j] - dm) - 0.5f * y * r2 * r2 * dv;
                float Phi = 0.5f * (1.f + erff(y * 0.70710678118654752f));
                float phi = 0.3989422804014327f * expf(-0.5f * y * y);
                g_h1g[(size_t)r * HD + n] = y * Phi;
                g_th [(size_t)r * HD + n] = (Phi + y * phi) * dy;
            }
        }
        __syncwarp();
    }
}

// ---------------- k3: big decoder GEMM (primal + tangent) ---------------------
// block: 256 = (tx 32) x (ty 8); 32 rows/block, 4 rows/thread, 4 cols/thread
__global__ void __launch_bounds__(256) k3_dec(
    const float* __restrict__ w2, const float* __restrict__ b2)
{
    __shared__ float Hs[32][100];
    __shared__ float Ts[32][100];
    int tid = threadIdx.x, tx = tid & 31, ty = tid >> 5;
    int m0 = blockIdx.x * 32;

    for (int i = tid; i < 32 * HD; i += 256) {
        int m = i / HD, k = i - m * HD;
        Hs[m][k] = g_h1g[(size_t)(m0 + m) * HD + k];
        Ts[m][k] = g_th [(size_t)(m0 + m) * HD + k];
    }
    __syncthreads();

    float accl[4] = {0.f, 0.f, 0.f, 0.f};
    float acct[4] = {0.f, 0.f, 0.f, 0.f};

    for (int nc = 0; nc < 16; nc++) {
        int n = nc * 128 + tx * 4;
        if (n >= XD) continue;
        float a[4][4], t[4][4];
#pragma unroll
        for (int i = 0; i < 4; i++)
#pragma unroll
            for (int j = 0; j < 4; j++) { a[i][j] = 0.f; t[i][j] = 0.f; }

        const float* wp = w2 + n;
#pragma unroll 4
        for (int k = 0; k < HD; k++) {
            float4 w = *(const float4*)(wp + (size_t)k * XD);
#pragma unroll
            for (int i = 0; i < 4; i++) {
                float h  = Hs[ty * 4 + i][k];
                float tv = Ts[ty * 4 + i][k];
                a[i][0] += h * w.x;  a[i][1] += h * w.y;
                a[i][2] += h * w.z;  a[i][3] += h * w.w;
                t[i][0] += tv * w.x; t[i][1] += tv * w.y;
                t[i][2] += tv * w.z; t[i][3] += tv * w.w;
            }
        }
        float4 bb = *(const float4*)(b2 + n);
        float bj[4] = {bb.x, bb.y, bb.z, bb.w};
#pragma unroll
        for (int i = 0; i < 4; i++) {
            int row = m0 + ty * 4 + i;
            float4 lo, to;
            float l0, tl0;
            float av;
            av = a[i][0] + bj[0]; l0 = softplusf(av); tl0 = sigmoidf(av) * t[i][0];
            lo.x = l0; to.x = tl0; accl[i] += l0; acct[i] += tl0;
            av = a[i][1] + bj[1]; l0 = softplusf(av); tl0 = sigmoidf(av) * t[i][1];
            lo.y = l0; to.y = tl0; accl[i] += l0; acct[i] += tl0;
            av = a[i][2] + bj[2]; l0 = softplusf(av); tl0 = sigmoidf(av) * t[i][2];
            lo.z = l0; to.z = tl0; accl[i] += l0; acct[i] += tl0;
            av = a[i][3] + bj[3]; l0 = softplusf(av); tl0 = sigmoidf(av) * t[i][3];
            lo.w = l0; to.w = tl0; accl[i] += l0; acct[i] += tl0;
            *(float4*)&g_ld [(size_t)row * XD + n] = lo;
            *(float4*)&g_tld[(size_t)row * XD + n] = to;
        }
    }
#pragma unroll
    for (int i = 0; i < 4; i++) {
        float sl = wsum(accl[i]);
        float s2 = wsum(acct[i]);
        if (tx == 0) {
            g_sld [m0 + ty * 4 + i] = sl;
            g_stld[m0 + ty * 4 + i] = s2;
        }
    }
}

// ---------------- k4: finalize s_hat / diff / pu ------------------------------
__global__ void __launch_bounds__(256) k4_fin(
    float* __restrict__ o_shat, float* __restrict__ o_diff, float* __restrict__ o_pu)
{
    int idx = blockIdx.x * 256 + threadIdx.x;      // BB*500 total
    int r = idx / 500;
    int c = (idx - r * 500) * 4;

    float m  = g_sld [r] * (1.f / XD);
    float mt = g_stld[r] * (1.f / XD);
    float rm = 1.f / m;
    float cm = mt * rm * rm;

    float4 l  = *(const float4*)&g_ld [(size_t)r * XD + c];
    float4 tl = *(const float4*)&g_tld[(size_t)r * XD + c];
    float4 be = *(const float4*)&g_beta[c];
    float4 ga = *(const float4*)&g_gamma[c];

    float4 sh, df, pu;
    sh.x = l.x * rm; df.x = 0.01f * (tl.x * rm - l.x * cm);
    sh.y = l.y * rm; df.y = 0.01f * (tl.y * rm - l.y * cm);
    sh.z = l.z * rm; df.z = 0.01f * (tl.z * rm - l.z * cm);
    sh.w = l.w * rm; df.w = 0.01f * (tl.w * rm - l.w * cm);
    pu.x = fmaxf((df.x + sh.x * ga.x) / be.x, 0.f);
    pu.y = fmaxf((df.y + sh.y * ga.y) / be.y, 0.f);
    pu.z = fmaxf((df.z + sh.z * ga.z) / be.z, 0.f);
    pu.w = fmaxf((df.w + sh.w * ga.w) / be.w, 0.f);

    *(float4*)&o_shat[(size_t)r * XD + c] = sh;
    *(float4*)&o_diff[(size_t)r * XD + c] = df;
    *(float4*)&o_pu  [(size_t)r * XD + c] = pu;
}

// ---------------- launcher ----------------------------------------------------
extern "C" void kernel_launch(void* const* d_in, const int* in_sizes, int n_in,
                              void* d_out, int out_size)
{
    const float* s      = (const float*)d_in[0];
    const float* u      = (const float*)d_in[1];
    const float* eps_z  = (const float*)d_in[2];
    const float* eps_d  = (const float*)d_in[3];
    const float* ez_w1  = (const float*)d_in[4];
    const float* ez_b1  = (const float*)d_in[5];
    const float* ez_w2  = (const float*)d_in[6];
    const float* ez_b2  = (const float*)d_in[7];
    const float* ez_wmu = (const float*)d_in[8];
    const float* ez_bmu = (const float*)d_in[9];
    const float* ez_wlv = (const float*)d_in[10];
    const float* ez_blv = (const float*)d_in[11];
    const float* ed_w1  = (const float*)d_in[12];
    const float* ed_b1  = (const float*)d_in[13];
    const float* ed_wmu = (const float*)d_in[14];
    const float* ed_bmu = (const float*)d_in[15];
    const float* ed_wlv = (const float*)d_in[16];
    const float* ed_blv = (const float*)d_in[17];
    const float* dz_w1  = (const float*)d_in[18];
    const float* dz_b1  = (const float*)d_in[19];
    const float* dz_w2  = (const float*)d_in[20];
    const float* dz_b2  = (const float*)d_in[21];
    const float* logb   = (const float*)d_in[22];
    const float* logg   = (const float*)d_in[23];

    float* out = (float*)d_out;
    float* o_z    = out;
    float* o_dz   = o_z    + (size_t)BB * ZD;
    float* o_muz  = o_dz   + (size_t)BB * ZD;
    float* o_scz  = o_muz  + (size_t)BB * ZD;
    float* o_mud  = o_scz  + (size_t)BB * ZD;
    float* o_scd  = o_mud  + (size_t)BB * ZD;
    float* o_shat = o_scd  + (size_t)BB * ZD;
    float* o_diff = o_shat + (size_t)BB * XD;
    float* o_pu   = o_diff + (size_t)BB * XD;

    const int smem2 = K2_SMEM_FLOATS * 4;
    cudaFuncSetAttribute(k2_mid, cudaFuncAttributeMaxDynamicSharedMemorySize, smem2);

    k0_rates<<<8, 256>>>(logb, logg);
    k1_enc1<<<BB / 64, 256>>>(s, u, ez_w1, ez_b1);
    k2_mid<<<512, 256, smem2>>>(eps_z, eps_d,
                                ez_w2, ez_b2, ez_wmu, ez_bmu, ez_wlv, ez_blv,
                                ed_w1, ed_b1, ed_wmu, ed_bmu, ed_wlv, ed_blv,
                                dz_w1, dz_b1,
                                o_z, o_dz, o_muz, o_scz, o_mud, o_scd);
    k3_dec<<<BB / 32, 256>>>(dz_w2, dz_b2);
    k4_fin<<<(BB * 500) / 256, 256>>>(o_shat, o_diff, o_pu);
}

// round 2
// speedup vs baseline: 1.1405x; 1.1405x over previous
#include <cuda_runtime.h>
#include <math.h>

#define BB 16384
#define XD 2000
#define HD 100
#define ZD 20
#define KTOT (2*XD)      // 4000
#define LN_EPS 1e-5f

// ---------------- scratch (static device globals; no allocations) -------------
__device__ float g_h1 [(size_t)BB*HD];
__device__ float g_h1g[(size_t)BB*HD];
__device__ float g_th [(size_t)BB*HD];
__device__ float g_ld [(size_t)BB*XD];
__device__ float g_tld[(size_t)BB*XD];
__device__ float g_beta [XD];
__device__ float g_gamma[XD];

// ---------------- helpers -----------------------------------------------------
__device__ __forceinline__ float softplusf(float x) {
    return fmaxf(x, 0.f) + log1pf(expf(-fabsf(x)));
}
__device__ __forceinline__ float sigmoidf(float x) {
    return 1.f / (1.f + expf(-x));
}
__device__ __forceinline__ float geluf(float x) {
    return 0.5f * x * (1.f + erff(x * 0.70710678118654752f));
}
__device__ __forceinline__ float wsum(float v) {
#pragma unroll
    for (int o = 16; o; o >>= 1) v += __shfl_xor_sync(0xffffffffu, v, o);
    return v;
}

// ---------------- k0: beta/gamma precompute ----------------------------------
__global__ void k0_rates(const float* __restrict__ lb, const float* __restrict__ lg) {
    int i = blockIdx.x * blockDim.x + threadIdx.x;
    if (i < XD) {
        g_beta[i]  = softplusf(lb[i]);   // * DT (=1)
        g_gamma[i] = softplusf(lg[i]);
    }
}

// ---------------- k1: h1 = gelu(LN([s,u]@W1 + b1)) ----------------------------
// M=32 rows/block (512 blocks), N=128 (100 valid), KC=32 double-buffered stages,
// register-prefetch staging, ONE __syncthreads per stage.
#define KC 32
__global__ void __launch_bounds__(256) k1_enc1(
    const float* __restrict__ s, const float* __restrict__ u,
    const float* __restrict__ w1, const float* __restrict__ b1)
{
    __shared__ float Ast[2][KC][36];    // [k][m] transposed, padded
    __shared__ float Ws [2][KC][132];   // [k][n], cols 100..127 zeroed

    int tid = threadIdx.x;
    int tn = tid & 31, tm = tid >> 5;
    int m0 = blockIdx.x * 32;

    // zero the pad columns of both W buffers (cols 100..127)
    for (int i = tid; i < 2 * KC * 28; i += 256) {
        int b = i / (KC * 28);
        int r = (i / 28) % KC;
        int c = 100 + (i % 28);
        Ws[b][r][c] = 0.f;
    }

    // staging thread mapping
    int aM  = tid >> 3;            // 0..31 row within tile
    int aK4 = (tid & 7) * 4;       // 0..28 k offset (float4)
    // W: 800 float4 per stage -> 3 per thread + 32 extra by tid<32
    int wRow[4], wC4[4];
#pragma unroll
    for (int t = 0; t < 4; t++) {
        int lin = tid + t * 256;   // t==3 only valid for tid<32
        wRow[t] = lin / 25;
        wC4 [t] = (lin - wRow[t] * 25) * 4;
    }

    float4 aReg;
    float4 wReg[4];

    // prefetch stage 0
    {
        int gk = 0 + aK4;
        const float* base = (gk < XD) ? &s[(size_t)(m0 + aM) * XD + gk]
                                      : &u[(size_t)(m0 + aM) * XD + gk - XD];
        aReg = *(const float4*)base;
#pragma unroll
        for (int t = 0; t < 3; t++)
            wReg[t] = *(const float4*)&w1[(size_t)(0 + wRow[t]) * HD + wC4[t]];
        if (tid < 32)
            wReg[3] = *(const float4*)&w1[(size_t)(0 + wRow[3]) * HD + wC4[3]];
    }

    float acc[4][4];
#pragma unroll
    for (int i = 0; i < 4; i++)
#pragma unroll
        for (int j = 0; j < 4; j++) acc[i][j] = 0.f;

    float bv[4] = {0.f, 0.f, 0.f, 0.f};
    if (tn < 25) {
        float4 b = *(const float4*)&b1[tn * 4];
        bv[0] = b.x; bv[1] = b.y; bv[2] = b.z; bv[3] = b.w;
    }

    int buf = 0;
    for (int kb = 0; kb < KTOT; kb += KC) {
        // STS current stage from regs into buf
        Ast[buf][aK4 + 0][aM] = aReg.x;
        Ast[buf][aK4 + 1][aM] = aReg.y;
        Ast[buf][aK4 + 2][aM] = aReg.z;
        Ast[buf][aK4 + 3][aM] = aReg.w;
#pragma unroll
        for (int t = 0; t < 3; t++)
            *(float4*)&Ws[buf][wRow[t]][wC4[t]] = wReg[t];
        if (tid < 32)
            *(float4*)&Ws[buf][wRow[3]][wC4[3]] = wReg[3];
        __syncthreads();

        // prefetch next stage
        int kn = kb + KC;
        if (kn < KTOT) {
            int gk = kn + aK4;
            const float* base = (gk < XD) ? &s[(size_t)(m0 + aM) * XD + gk]
                                          : &u[(size_t)(m0 + aM) * XD + gk - XD];
            aReg = *(const float4*)base;
#pragma unroll
            for (int t = 0; t < 3; t++)
                wReg[t] = *(const float4*)&w1[(size_t)(kn + wRow[t]) * HD + wC4[t]];
            if (tid < 32)
                wReg[3] = *(const float4*)&w1[(size_t)(kn + wRow[3]) * HD + wC4[3]];
        }

        // compute current stage
#pragma unroll
        for (int k = 0; k < KC; k++) {
            float4 a = *(const float4*)&Ast[buf][k][tm * 4];
            float4 w = *(const float4*)&Ws [buf][k][tn * 4];
            float av[4] = {a.x, a.y, a.z, a.w};
#pragma unroll
            for (int i = 0; i < 4; i++) {
                acc[i][0] += av[i] * w.x;
                acc[i][1] += av[i] * w.y;
                acc[i][2] += av[i] * w.z;
                acc[i][3] += av[i] * w.w;
            }
        }
        buf ^= 1;
    }

    // per-row LN + GELU (lanes cover 128 cols, 100 valid; invalid lanes contribute 0)
#pragma unroll
    for (int i = 0; i < 4; i++) {
        int m = m0 + tm * 4 + i;
        float x[4], sm = 0.f, sq = 0.f;
#pragma unroll
        for (int j = 0; j < 4; j++) {
            x[j] = acc[i][j] + bv[j];
            sm += x[j];
            sq += x[j] * x[j];
        }
        sm = wsum(sm); sq = wsum(sq);
        float mean = sm * (1.f / HD);
        float var  = sq * (1.f / HD) - mean * mean;
        float rs = rsqrtf(var + LN_EPS);
        if (tn < 25) {
            float4 o;
            o.x = geluf((x[0] - mean) * rs);
            o.y = geluf((x[1] - mean) * rs);
            o.z = geluf((x[2] - mean) * rs);
            o.w = geluf((x[3] - mean) * rs);
            *(float4*)&g_h1[(size_t)m * HD + tn * 4] = o;
        }
    }
}

// ---------------- k2: everything small, one warp per row ----------------------
#define K2_SMEM_FLOATS (22380 + 8*264)
__global__ void __launch_bounds__(256) k2_mid(
    const float* __restrict__ eps_z, const float* __restrict__ eps_d,
    const float* __restrict__ w2, const float* __restrict__ b2,
    const float* __restrict__ wmu, const float* __restrict__ bmu,
    const float* __restrict__ wlv, const float* __restrict__ blv,
    const float* __restrict__ edw1, const float* __restrict__ edb1,
    const float* __restrict__ edwmu, const float* __restrict__ edbmu,
    const float* __restrict__ edwlv, const float* __restrict__ edblv,
    const float* __restrict__ dzw1, const float* __restrict__ dzb1,
    float* __restrict__ o_z, float* __restrict__ o_dz,
    float* __restrict__ o_muz, float* __restrict__ o_scz,
    float* __restrict__ o_mud, float* __restrict__ o_scd)
{
    extern __shared__ float sm2[];
    float* sw2    = sm2;              // 10000
    float* swmu   = sw2 + 10000;      // 2000
    float* swlv   = swmu + 2000;      // 2000
    float* sb2    = swlv + 2000;      // 100
    float* sbmu   = sb2 + 100;        // 20
    float* sblv   = sbmu + 20;        // 20
    float* sedw1  = sblv + 20;        // 2000
    float* sedb1  = sedw1 + 2000;     // 100
    float* sedwmu = sedb1 + 100;      // 2000
    float* sedbmu = sedwmu + 2000;    // 20
    float* sedwlv = sedbmu + 20;      // 2000
    float* sedblv = sedwlv + 2000;    // 20
    float* sdzw1  = sedblv + 20;      // 2000
    float* sdzb1  = sdzw1 + 2000;     // 100
    float* wbuf   = sdzb1 + 100;      // 8 warps * 264

    {
        int t = threadIdx.x, nt = blockDim.x;
        for (int i = t; i < 10000; i += nt) sw2[i] = w2[i];
        for (int i = t; i < 2000; i += nt) { swmu[i] = wmu[i]; swlv[i] = wlv[i]; }
        for (int i = t; i < 2000; i += nt) { sedw1[i] = edw1[i]; sdzw1[i] = dzw1[i]; }
        for (int i = t; i < 2000; i += nt) { sedwmu[i] = edwmu[i]; sedwlv[i] = edwlv[i]; }
        for (int i = t; i < 100; i += nt) { sb2[i] = b2[i]; sedb1[i] = edb1[i]; sdzb1[i] = dzb1[i]; }
        if (t < 20) { sbmu[t] = bmu[t]; sblv[t] = blv[t]; sedbmu[t] = edbmu[t]; sedblv[t] = edblv[t]; }
    }
    __syncthreads();

    int wid = threadIdx.x >> 5, lane = threadIdx.x & 31;
    float* B0 = wbuf + wid * 264;
    float* B1 = B0 + 132;
    int nwarps = gridDim.x * 8;

    for (int r = blockIdx.x * 8 + wid; r < BB; r += nwarps) {
        // load h1 row
        for (int i = lane; i < HD; i += 32) B0[i] = g_h1[(size_t)r * HD + i];
        __syncwarp();

        // ---- h2 = gelu(LN(h1@w2 + b2)) ----
        float x[4];
#pragma unroll
        for (int j = 0; j < 4; j++) {
            int n = lane + 32 * j;
            float acc = 0.f;
            if (n < HD) {
                acc = sb2[n];
                for (int k = 0; k < HD; k++) acc += B0[k] * sw2[k * HD + n];
            }
            x[j] = acc;
        }
        float smv = x[0] + x[1] + x[2] + x[3];
        float sqv = x[0]*x[0] + x[1]*x[1] + x[2]*x[2] + x[3]*x[3];
        smv = wsum(smv); sqv = wsum(sqv);
        float mean = smv * (1.f / HD);
        float rs = rsqrtf(sqv * (1.f / HD) - mean * mean + LN_EPS);
#pragma unroll
        for (int j = 0; j < 4; j++) {
            int n = lane + 32 * j;
            if (n < HD) B1[n] = geluf((x[j] - mean) * rs);
        }
        __syncwarp();

        // ---- z heads ----
        if (lane < ZD) {
            float mu = sbmu[lane], lv = sblv[lane];
            for (int k = 0; k < HD; k++) {
                float h = B1[k];
                mu += h * swmu[k * ZD + lane];
                lv += h * swlv[k * ZD + lane];
            }
            float sc = softplusf(lv);
            float z = mu + sc * eps_z[(size_t)r * ZD + lane];
            o_z  [(size_t)r * ZD + lane] = z;
            o_muz[(size_t)r * ZD + lane] = mu;
            o_scz[(size_t)r * ZD + lane] = sc;
            B0[lane] = z;
        }
        __syncwarp();

        // ---- hd = gelu(LN(z@ed_w1 + b)) ----
#pragma unroll
        for (int j = 0; j < 4; j++) {
            int n = lane + 32 * j;
            float acc = 0.f;
            if (n < HD) {
                acc = sedb1[n];
                for (int k = 0; k < ZD; k++) acc += B0[k] * sedw1[k * HD + n];
            }
            x[j] = acc;
        }
        smv = x[0] + x[1] + x[2] + x[3];
        sqv = x[0]*x[0] + x[1]*x[1] + x[2]*x[2] + x[3]*x[3];
        smv = wsum(smv); sqv = wsum(sqv);
        mean = smv * (1.f / HD);
        rs = rsqrtf(sqv * (1.f / HD) - mean * mean + LN_EPS);
#pragma unroll
        for (int j = 0; j < 4; j++) {
            int n = lane + 32 * j;
            if (n < HD) B1[n] = geluf((x[j] - mean) * rs);
        }
        __syncwarp();

        // ---- d heads ----
        if (lane < ZD) {
            float mu = sedbmu[lane], lv = sedblv[lane];
            for (int k = 0; k < HD; k++) {
                float h = B1[k];
                mu += h * sedwmu[k * ZD + lane];
                lv += h * sedwlv[k * ZD + lane];
            }
            float sc = softplusf(lv);
            float dz = mu + sc * eps_d[(size_t)r * ZD + lane];
            o_dz [(size_t)r * ZD + lane] = dz;
            o_mud[(size_t)r * ZD + lane] = mu;
            o_scd[(size_t)r * ZD + lane] = sc;
            B0[32 + lane] = dz;
        }
        __syncwarp();

        // ---- decoder layer 1 with JVP: a1 = z@w1+b, t1 = dz@w1 ----
        float a[4], t[4];
#pragma unroll
        for (int j = 0; j < 4; j++) {
            int n = lane + 32 * j;
            float aa = 0.f, tt = 0.f;
            if (n < HD) {
                aa = sdzb1[n];
                for (int k = 0; k < ZD; k++) {
                    float w = sdzw1[k * HD + n];
                    aa += B0[k] * w;
                    tt += B0[32 + k] * w;
                }
            }
            a[j] = aa; t[j] = tt;
        }
        float sa = a[0]+a[1]+a[2]+a[3];
        float saa = a[0]*a[0]+a[1]*a[1]+a[2]*a[2]+a[3]*a[3];
        float st = t[0]+t[1]+t[2]+t[3];
        float sat = a[0]*t[0]+a[1]*t[1]+a[2]*t[2]+a[3]*t[3];
        sa = wsum(sa); saa = wsum(saa); st = wsum(st); sat = wsum(sat);
        float m  = sa * (1.f / HD);
        float v  = saa * (1.f / HD) - m * m;
        float r2 = rsqrtf(v + LN_EPS);
        float dm = st * (1.f / HD);
        float dv = 2.f * (sat * (1.f / HD) - m * dm);
#pragma unroll
        for (int j = 0; j < 4; j++) {
            int n = lane + 32 * j;
            if (n < HD) {
                float y  = (a[j] - m) * r2;
                float dy = r2 * (t[j] - dm) - 0.5f * y * r2 * r2 * dv;
                float Phi = 0.5f * (1.f + erff(y * 0.70710678118654752f));
                float phi = 0.3989422804014327f * expf(-0.5f * y * y);
                g_h1g[(size_t)r * HD + n] = y * Phi;
                g_th [(size_t)r * HD + n] = (Phi + y * phi) * dy;
            }
        }
        __syncwarp();
    }
}

// ---------------- k3: big decoder GEMM (primal + tangent), all-smem -----------
// Block tile M=64, N=128 (two 64-wide halves). W chunk fully resident in smem.
// 256 threads: tn=tid&15 (cols 4tn and 64+4tn), tm=tid>>4 (rows 4tm..4tm+3).
#define K3_SMEM_FLOATS (100*132 + 2*64*104)
__global__ void __launch_bounds__(256, 2) k3_dec(
    const float* __restrict__ w2, const float* __restrict__ b2)
{
    extern __shared__ float sm3[];
    float (*Ws)[132] = (float (*)[132])sm3;                      // 100 x 132
    float (*Hs)[104] = (float (*)[104])(sm3 + 100 * 132);        // 64 x 104
    float (*Ts)[104] = (float (*)[104])(sm3 + 100 * 132 + 64 * 104);

    int tid = threadIdx.x;
    int tn = tid & 15, tm = tid >> 4;
    int n0 = blockIdx.x * 128;
    int m0 = blockIdx.y * 64;

    // stage W chunk: 100 x 128 (invalid cols -> 0)
    for (int lin = tid; lin < 3200; lin += 256) {
        int k = lin >> 5, c4 = (lin & 31) * 4;
        float4 v = make_float4(0.f, 0.f, 0.f, 0.f);
        if (n0 + c4 < XD) v = *(const float4*)&w2[(size_t)k * XD + n0 + c4];
        *(float4*)&Ws[k][c4] = v;
    }
    // stage H, T tiles: 64 x 100
    for (int lin = tid; lin < 1600; lin += 256) {
        int m = lin / 25, k4 = (lin - m * 25) * 4;
        *(float4*)&Hs[m][k4] = *(const float4*)&g_h1g[(size_t)(m0 + m) * HD + k4];
        *(float4*)&Ts[m][k4] = *(const float4*)&g_th [(size_t)(m0 + m) * HD + k4];
    }
    __syncthreads();

    float aA[4][4], aB[4][4], tA[4][4], tB[4][4];
#pragma unroll
    for (int i = 0; i < 4; i++)
#pragma unroll
        for (int j = 0; j < 4; j++) { aA[i][j]=0.f; aB[i][j]=0.f; tA[i][j]=0.f; tB[i][j]=0.f; }

    for (int k = 0; k < HD; k++) {
        float4 wA = *(const float4*)&Ws[k][tn * 4];
        float4 wB = *(const float4*)&Ws[k][64 + tn * 4];
#pragma unroll
        for (int i = 0; i < 4; i++) {
            float h = Hs[tm * 4 + i][k];
            float t = Ts[tm * 4 + i][k];
            aA[i][0] += h * wA.x; aA[i][1] += h * wA.y; aA[i][2] += h * wA.z; aA[i][3] += h * wA.w;
            aB[i][0] += h * wB.x; aB[i][1] += h * wB.y; aB[i][2] += h * wB.z; aB[i][3] += h * wB.w;
            tA[i][0] += t * wA.x; tA[i][1] += t * wA.y; tA[i][2] += t * wA.z; tA[i][3] += t * wA.w;
            tB[i][0] += t * wB.x; tB[i][1] += t * wB.y; tB[i][2] += t * wB.z; tB[i][3] += t * wB.w;
        }
    }

    int nA = n0 + tn * 4;
    int nB = n0 + 64 + tn * 4;
    float4 bA = make_float4(0.f,0.f,0.f,0.f), bB = bA;
    if (nA < XD) bA = *(const float4*)&b2[nA];
    if (nB < XD) bB = *(const float4*)&b2[nB];

#pragma unroll
    for (int i = 0; i < 4; i++) {
        int row = m0 + tm * 4 + i;
        if (nA < XD) {
            float4 lo, to; float av;
            av = aA[i][0] + bA.x; lo.x = softplusf(av); to.x = sigmoidf(av) * tA[i][0];
            av = aA[i][1] + bA.y; lo.y = softplusf(av); to.y = sigmoidf(av) * tA[i][1];
            av = aA[i][2] + bA.z; lo.z = softplusf(av); to.z = sigmoidf(av) * tA[i][2];
            av = aA[i][3] + bA.w; lo.w = softplusf(av); to.w = sigmoidf(av) * tA[i][3];
            *(float4*)&g_ld [(size_t)row * XD + nA] = lo;
            *(float4*)&g_tld[(size_t)row * XD + nA] = to;
        }
        if (nB < XD) {
            float4 lo, to; float av;
            av = aB[i][0] + bB.x; lo.x = softplusf(av); to.x = sigmoidf(av) * tB[i][0];
            av = aB[i][1] + bB.y; lo.y = softplusf(av); to.y = sigmoidf(av) * tB[i][1];
            av = aB[i][2] + bB.z; lo.z = softplusf(av); to.z = sigmoidf(av) * tB[i][2];
            av = aB[i][3] + bB.w; lo.w = softplusf(av); to.w = sigmoidf(av) * tB[i][3];
            *(float4*)&g_ld [(size_t)row * XD + nB] = lo;
            *(float4*)&g_tld[(size_t)row * XD + nB] = to;
        }
    }
}

// ---------------- k4: per-row sums + finalize ---------------------------------
__global__ void __launch_bounds__(256) k4_fin(
    float* __restrict__ o_shat, float* __restrict__ o_diff, float* __restrict__ o_pu)
{
    __shared__ float red[16];
    int r = blockIdx.x;
    int tid = threadIdx.x;

    float4 l[2], tl[2];
    float sl = 0.f, st = 0.f;
#pragma unroll
    for (int j = 0; j < 2; j++) {
        int c = (tid + j * 256) * 4;
        if (c < XD) {
            l [j] = *(const float4*)&g_ld [(size_t)r * XD + c];
            tl[j] = *(const float4*)&g_tld[(size_t)r * XD + c];
            sl += l [j].x + l [j].y + l [j].z + l [j].w;
            st += tl[j].x + tl[j].y + tl[j].z + tl[j].w;
        }
    }
    sl = wsum(sl); st = wsum(st);
    int wid = tid >> 5, lane = tid & 31;
    if (lane == 0) { red[wid] = sl; red[8 + wid] = st; }
    __syncthreads();
    sl = red[0]+red[1]+red[2]+red[3]+red[4]+red[5]+red[6]+red[7];
    st = red[8]+red[9]+red[10]+red[11]+red[12]+red[13]+red[14]+red[15];

    float m  = sl * (1.f / XD);
    float mt = st * (1.f / XD);
    float rm = 1.f / m;
    float cm = mt * rm * rm;

#pragma unroll
    for (int j = 0; j < 2; j++) {
        int c = (tid + j * 256) * 4;
        if (c < XD) {
            float4 be = *(const float4*)&g_beta[c];
            float4 ga = *(const float4*)&g_gamma[c];
            float4 sh, df, pu;
            sh.x = l[j].x * rm; df.x = 0.01f * (tl[j].x * rm - l[j].x * cm);
            sh.y = l[j].y * rm; df.y = 0.01f * (tl[j].y * rm - l[j].y * cm);
            sh.z = l[j].z * rm; df.z = 0.01f * (tl[j].z * rm - l[j].z * cm);
            sh.w = l[j].w * rm; df.w = 0.01f * (tl[j].w * rm - l[j].w * cm);
            pu.x = fmaxf((df.x + sh.x * ga.x) / be.x, 0.f);
            pu.y = fmaxf((df.y + sh.y * ga.y) / be.y, 0.f);
            pu.z = fmaxf((df.z + sh.z * ga.z) / be.z, 0.f);
            pu.w = fmaxf((df.w + sh.w * ga.w) / be.w, 0.f);
            *(float4*)&o_shat[(size_t)r * XD + c] = sh;
            *(float4*)&o_diff[(size_t)r * XD + c] = df;
            *(float4*)&o_pu  [(size_t)r * XD + c] = pu;
        }
    }
}

// ---------------- launcher ----------------------------------------------------
extern "C" void kernel_launch(void* const* d_in, const int* in_sizes, int n_in,
                              void* d_out, int out_size)
{
    const float* s      = (const float*)d_in[0];
    const float* u      = (const float*)d_in[1];
    const float* eps_z  = (const float*)d_in[2];
    const float* eps_d  = (const float*)d_in[3];
    const float* ez_w1  = (const float*)d_in[4];
    const float* ez_b1  = (const float*)d_in[5];
    const float* ez_w2  = (const float*)d_in[6];
    const float* ez_b2  = (const float*)d_in[7];
    const float* ez_wmu = (const float*)d_in[8];
    const float* ez_bmu = (const float*)d_in[9];
    const float* ez_wlv = (const float*)d_in[10];
    const float* ez_blv = (const float*)d_in[11];
    const float* ed_w1  = (const float*)d_in[12];
    const float* ed_b1  = (const float*)d_in[13];
    const float* ed_wmu = (const float*)d_in[14];
    const float* ed_bmu = (const float*)d_in[15];
    const float* ed_wlv = (const float*)d_in[16];
    const float* ed_blv = (const float*)d_in[17];
    const float* dz_w1  = (const float*)d_in[18];
    const float* dz_b1  = (const float*)d_in[19];
    const float* dz_w2  = (const float*)d_in[20];
    const float* dz_b2  = (const float*)d_in[21];
    const float* logb   = (const float*)d_in[22];
    const float* logg   = (const float*)d_in[23];

    float* out = (float*)d_out;
    float* o_z    = out;
    float* o_dz   = o_z    + (size_t)BB * ZD;
    float* o_muz  = o_dz   + (size_t)BB * ZD;
    float* o_scz  = o_muz  + (size_t)BB * ZD;
    float* o_mud  = o_scz  + (size_t)BB * ZD;
    float* o_scd  = o_mud  + (size_t)BB * ZD;
    float* o_shat = o_scd  + (size_t)BB * ZD;
    float* o_diff = o_shat + (size_t)BB * XD;
    float* o_pu   = o_diff + (size_t)BB * XD;

    const int smem2 = K2_SMEM_FLOATS * 4;
    const int smem3 = K3_SMEM_FLOATS * 4;
    cudaFuncSetAttribute(k2_mid, cudaFuncAttributeMaxDynamicSharedMemorySize, smem2);
    cudaFuncSetAttribute(k3_dec, cudaFuncAttributeMaxDynamicSharedMemorySize, smem3);

    k0_rates<<<8, 256>>>(logb, logg);
    k1_enc1<<<BB / 32, 256>>>(s, u, ez_w1, ez_b1);
    k2_mid<<<512, 256, smem2>>>(eps_z, eps_d,
                                ez_w2, ez_b2, ez_wmu, ez_bmu, ez_wlv, ez_blv,
                                ed_w1, ed_b1, ed_wmu, ed_bmu, ed_wlv, ed_blv,
                                dz_w1, dz_b1,
                                o_z, o_dz, o_muz, o_scz, o_mud, o_scd);
    dim3 g3(16, 256);
    k3_dec<<<g3, 256, smem3>>>(dz_w2, dz_b2);
    k4_fin<<<BB, 256>>>(o_shat, o_diff, o_pu);
}